// round 12
// baseline (speedup 1.0000x reference)
#include <cuda_runtime.h>
#include <math.h>
#include <stdint.h>

#define SEQ    2048
#define BATCH  2
#define TOK    4096
#define DIM    1024
#define NHEAD  16
#define KVHEAD 4
#define HDIM   64
#define NLAYER 8
#define FF     4096
#define VOCAB  32000

// ---------------- f32 scratch ----------------
__device__ float g_h   [TOK * DIM];
__device__ float g_qkv [TOK * 1536];          // qkv slab; also reused as C-staging (16MB needed, 24MB avail)
__device__ float g_att [TOK * DIM];
__device__ float g_f13 [TOK * 8192];
__device__ float g_cos [SEQ * 32];
__device__ float g_sin [SEQ * 32];
// ---------------- int8 quantized operands ----------------
// A-side rows: [a0 | a0 | a1] (3K), B-side rows: [b0 | b1 | b0] (3K)
__device__ int8_t q_x   [TOK * 3072];           __device__ float s_x  [TOK];
__device__ int8_t q_att [TOK * 3072];           __device__ float s_att[TOK];
__device__ int8_t q_f1  [(size_t)TOK * 12288];  __device__ float s_f1 [TOK];
__device__ int8_t q_wqkv[(size_t)NLAYER * 1536 * 3072];  __device__ float s_wqkv[NLAYER * 1536];
__device__ int8_t q_wo  [(size_t)NLAYER * 1024 * 3072];  __device__ float s_wo  [NLAYER * 1024];
__device__ int8_t q_w13 [(size_t)NLAYER * 8192 * 3072];  __device__ float s_w13 [NLAYER * 8192];
__device__ int8_t q_w2  [(size_t)NLAYER * 1024 * 12288]; __device__ float s_w2  [NLAYER * 1024];
__device__ int8_t q_emb [(size_t)VOCAB * 3072];          __device__ float s_emb [VOCAB];

// ---------------- block max-reduce helper ----------------
__device__ __forceinline__ float block_reduce_max(float v) {
    #pragma unroll
    for (int o = 16; o; o >>= 1) v = fmaxf(v, __shfl_xor_sync(0xffffffffu, v, o));
    __shared__ float red[8]; __shared__ float out;
    if ((threadIdx.x & 31) == 0) red[threadIdx.x >> 5] = v;
    __syncthreads();
    if (threadIdx.x == 0) {
        float m = red[0];
        #pragma unroll
        for (int i = 1; i < 8; i++) m = fmaxf(m, red[i]);
        out = m;
    }
    __syncthreads();
    return out;
}

// ---------------- generic row quantizer (block per row) ----------------
// BSIDE=0: out row = [a0|a0|a1];  BSIDE=1: out row = [b0|b1|b0]
template <int BSIDE>
__global__ __launch_bounds__(256) void quant_row_kernel(
    const float* __restrict__ in, int K, int8_t* __restrict__ out,
    float* __restrict__ scale, int rows_pl, size_t lstride, int row_off, int srows) {
    int rg = blockIdx.x, tid = threadIdx.x;
    int l = rg / rows_pl, r = rg % rows_pl;
    const float* x = in + (size_t)rg * K;
    int8_t* o = out + (size_t)l * lstride + (size_t)(row_off + r) * (3 * K);
    const int it = K / 256;
    float v[16];
    float mx = 0.f;
    for (int i = 0; i < it; i++) { v[i] = x[tid + i * 256]; mx = fmaxf(mx, fabsf(v[i])); }
    mx = block_reduce_max(mx);
    float s  = (mx > 0.f) ? mx / 127.f : 1.f;
    float inv = (mx > 0.f) ? 127.f / mx : 0.f;
    for (int i = 0; i < it; i++) {
        int d = tid + i * 256;
        float f  = v[i] * inv;
        float a0 = rintf(f);
        float a1 = rintf((f - a0) * 128.f);
        int8_t i0 = (int8_t)(int)a0, i1 = (int8_t)(int)a1;
        if (BSIDE) { o[d] = i0; o[K + d] = i1; o[2 * K + d] = i0; }
        else       { o[d] = i0; o[K + d] = i0; o[2 * K + d] = i1; }
    }
    if (tid == 0) scale[l * srows + row_off + r] = s;
}

// ---------------- RoPE tables ----------------
__global__ void rope_init_kernel() {
    int t = blockIdx.x, j = threadIdx.x;
    double inv   = pow(10000.0, -(2.0 * j) / 64.0);
    double r     = 81920.0 * inv / (2.0 * M_PI);
    double gamma = (r - 1.0) / 31.0;
    gamma = gamma < 0.0 ? 0.0 : (gamma > 1.0 ? 1.0 : gamma);
    double inv2  = inv * ((1.0 - gamma) / 40.0 + gamma);
    double c     = sqrt(0.1 * log(40.0) + 1.0);
    double ang   = (double)t * inv2 / c;
    g_cos[t * 32 + j] = (float)cos(ang);
    g_sin[t * 32 + j] = (float)sin(ang);
}

__global__ void embed_kernel(const int* __restrict__ ids, const float* __restrict__ emb) {
    int t = blockIdx.x;
    const float* src = emb + (size_t)ids[t] * DIM;
    float* dst = g_h + (size_t)t * DIM;
    for (int d = threadIdx.x; d < DIM; d += blockDim.x) dst[d] = src[d];
}

// ---------------- rmsnorm + int8 quantize (fused) ----------------
__global__ __launch_bounds__(256) void rmsnorm_quant_kernel(
    const float* __restrict__ x, const float* __restrict__ w,
    int8_t* __restrict__ o, float* __restrict__ sc) {
    int row = blockIdx.x, tid = threadIdx.x;
    const float* xr = x + (size_t)row * DIM;
    float v[4], wv[4];
    float ss = 0.f;
    #pragma unroll
    for (int i = 0; i < 4; i++) {
        int d = tid + i * 256;
        v[i] = xr[d]; wv[i] = w[d];
        ss += v[i] * v[i];
    }
    #pragma unroll
    for (int off = 16; off; off >>= 1) ss += __shfl_xor_sync(0xffffffffu, ss, off);
    __shared__ float red[8]; __shared__ float rsv;
    if ((tid & 31) == 0) red[tid >> 5] = ss;
    __syncthreads();
    if (tid == 0) {
        float t = 0.f;
        #pragma unroll
        for (int i = 0; i < 8; i++) t += red[i];
        rsv = rsqrtf(t / (float)DIM + 1e-6f);
    }
    __syncthreads();
    float rs = rsv;
    float mx = 0.f;
    #pragma unroll
    for (int i = 0; i < 4; i++) { v[i] = v[i] * rs * wv[i]; mx = fmaxf(mx, fabsf(v[i])); }
    mx = block_reduce_max(mx);
    float s  = (mx > 0.f) ? mx / 127.f : 1.f;
    float inv = (mx > 0.f) ? 127.f / mx : 0.f;
    int8_t* orow = o + (size_t)row * 3072;
    #pragma unroll
    for (int i = 0; i < 4; i++) {
        int d = tid + i * 256;
        float f  = v[i] * inv;
        float a0 = rintf(f);
        float a1 = rintf((f - a0) * 128.f);
        orow[d] = (int8_t)(int)a0;
        orow[1024 + d] = (int8_t)(int)a0;
        orow[2048 + d] = (int8_t)(int)a1;
    }
    if (tid == 0) sc[row] = s;
}

// ---------------- SwiGLU + int8 quantize (fused, block per row) ----------------
__global__ __launch_bounds__(256) void swiglu_quant_kernel() {
    int row = blockIdx.x, tid = threadIdx.x;
    const float* f1 = g_f13 + (size_t)row * 8192;
    const float* f3 = f1 + 4096;
    float u[16];
    float mx = 0.f;
    #pragma unroll
    for (int i = 0; i < 16; i++) {
        int d = tid + i * 256;
        float a = f1[d];
        u[i] = (a / (1.f + __expf(-a))) * f3[d];
        mx = fmaxf(mx, fabsf(u[i]));
    }
    mx = block_reduce_max(mx);
    float s  = (mx > 0.f) ? mx / 127.f : 1.f;
    float inv = (mx > 0.f) ? 127.f / mx : 0.f;
    int8_t* o = q_f1 + (size_t)row * 12288;
    #pragma unroll
    for (int i = 0; i < 16; i++) {
        int d = tid + i * 256;
        float f  = u[i] * inv;
        float a0 = rintf(f);
        float a1 = rintf((f - a0) * 128.f);
        o[d] = (int8_t)(int)a0;
        o[4096 + d] = (int8_t)(int)a0;
        o[8192 + d] = (int8_t)(int)a1;
    }
    if (tid == 0) s_f1[row] = s;
}

// ================= int8 tensor-core GEMM (IMMA m16n8k32) =================
// CTA tile 128x256, BK=128 s8 (128B rows, byte-identical layout to R11's
// proven bf16 BK=64 kernel), 2-stage cp.async, warp 64x64, s32 acc.
// FIN=0: C = (float)sum(a0*b0)  (exact staging)
// FIN=1: C = sA[i]*sB[j]*(C0 + (float)acc/128) (+R)
#define BM 128
#define BN 256
#define BKE 128                            // int8 k per tile
#define A_BYTES (BM * BKE)                 // 16384
#define B_BYTES (BN * BKE)                 // 32768
#define STAGE_BYTES (A_BYTES + B_BYTES)    // 49152
#define SMEM_DYN (2 * STAGE_BYTES)         // 98304

#define CP_ASYNC16(dst, src) \
    asm volatile("cp.async.cg.shared.global [%0], [%1], 16;" :: "r"(dst), "l"(src))
#define CP_COMMIT()  asm volatile("cp.async.commit_group;")
#define CP_WAIT1()   asm volatile("cp.async.wait_group 1;")
#define LDSM_X4(r0, r1, r2, r3, addr) \
    asm volatile("ldmatrix.sync.aligned.m8n8.x4.shared.b16 {%0,%1,%2,%3}, [%4];" \
        : "=r"(r0), "=r"(r1), "=r"(r2), "=r"(r3) : "r"(addr))
#define MMA_S8(c, a0, a1, a2, a3, b0, b1) \
    asm volatile("mma.sync.aligned.m16n8k32.row.col.s32.s8.s8.s32 " \
        "{%0,%1,%2,%3}, {%4,%5,%6,%7}, {%8,%9}, {%0,%1,%2,%3};" \
        : "+r"(c[0]), "+r"(c[1]), "+r"(c[2]), "+r"(c[3]) \
        : "r"(a0), "r"(a1), "r"(a2), "r"(a3), "r"(b0), "r"(b1))

template <int RES, int FIN>
__global__ __launch_bounds__(256) void gemm_i8(
    const int8_t* __restrict__ A, const int8_t* __restrict__ W,
    const float* __restrict__ C0, const float* __restrict__ R,
    float* __restrict__ C,
    const float* __restrict__ sA, const float* __restrict__ sB,
    int N, int Klen, int lda, int ldb) {
    extern __shared__ __align__(16) char smem[];
    const int tid  = threadIdx.x;
    const int lane = tid & 31;
    const int wid  = tid >> 5;
    const int wm   = wid >> 2;
    const int wn   = wid & 3;
    const int bm   = blockIdx.y * BM;
    const int bn   = blockIdx.x * BN;
    const uint32_t smem_u = (uint32_t)__cvta_generic_to_shared(smem);

    const int lrow = tid >> 3;
    const int lcol = tid & 7;
    const int8_t* AgBase = A + (size_t)bm * lda;
    const int8_t* WgBase = W + (size_t)bn * ldb;

    const int flr = lane & 15;
    const int fhi = lane >> 4;
    int aRow[4], aXor[4];
    #pragma unroll
    for (int i = 0; i < 4; i++) { aRow[i] = wm * 64 + i * 16 + flr; aXor[i] = aRow[i] & 7; }
    const int bkf = (lane >> 3) & 1;
    int bRow[4], bXor[4];
    #pragma unroll
    for (int p = 0; p < 4; p++) {
        bRow[p] = wn * 64 + (lane & 7) + fhi * 8 + p * 16;
        bXor[p] = bRow[p] & 7;
    }

    int acc[4][8][4];
    #pragma unroll
    for (int i = 0; i < 4; i++)
        #pragma unroll
        for (int j = 0; j < 8; j++)
            #pragma unroll
            for (int q = 0; q < 4; q++) acc[i][j][q] = 0;

    const int nk = Klen / BKE;

    auto load_stage = [&](int kt) {
        uint32_t base = smem_u + (kt & 1) * STAGE_BYTES;
        int k0 = kt * BKE;
        #pragma unroll
        for (int it = 0; it < 4; it++) {
            int r = lrow + it * 32;
            uint32_t dst = base + r * 128 + ((lcol ^ (r & 7)) << 4);
            CP_ASYNC16(dst, AgBase + (size_t)r * lda + k0 + lcol * 16);
        }
        uint32_t bb = base + A_BYTES;
        #pragma unroll
        for (int it = 0; it < 8; it++) {
            int r = lrow + it * 32;
            uint32_t dst = bb + r * 128 + ((lcol ^ (r & 7)) << 4);
            CP_ASYNC16(dst, WgBase + (size_t)r * ldb + k0 + lcol * 16);
        }
    };

    load_stage(0);
    CP_COMMIT();

    for (int kt = 0; kt < nk; kt++) {
        if (kt + 1 < nk) load_stage(kt + 1);
        CP_COMMIT();
        CP_WAIT1();
        __syncthreads();

        uint32_t cbase = smem_u + (kt & 1) * STAGE_BYTES;
        #pragma unroll
        for (int s = 0; s < 4; s++) {
            uint32_t af[4][4];
            #pragma unroll
            for (int i = 0; i < 4; i++) {
                uint32_t addr = cbase + aRow[i] * 128 + (((2 * s + fhi) ^ aXor[i]) << 4);
                LDSM_X4(af[i][0], af[i][1], af[i][2], af[i][3], addr);
            }
            #pragma unroll
            for (int p = 0; p < 4; p++) {
                uint32_t addr = cbase + (uint32_t)A_BYTES + bRow[p] * 128 +
                                (((2 * s + bkf) ^ bXor[p]) << 4);
                uint32_t b0, b1, b2, b3;
                LDSM_X4(b0, b1, b2, b3, addr);
                #pragma unroll
                for (int i = 0; i < 4; i++) {
                    MMA_S8(acc[i][2 * p],     af[i][0], af[i][1], af[i][2], af[i][3], b0, b1);
                    MMA_S8(acc[i][2 * p + 1], af[i][0], af[i][1], af[i][2], af[i][3], b2, b3);
                }
            }
        }
        __syncthreads();
    }

    const int gid = lane >> 2, tig = lane & 3;
    const float inv128 = 0.0078125f;
    #pragma unroll
    for (int i = 0; i < 4; i++) {
        int r0 = bm + wm * 64 + i * 16 + gid;
        float sa0 = 0.f, sa1 = 0.f;
        if (FIN) { sa0 = sA[r0]; sa1 = sA[r0 + 8]; }
        #pragma unroll
        for (int j = 0; j < 8; j++) {
            int c0 = bn + wn * 64 + j * 8 + tig * 2;
            size_t o0 = (size_t)r0 * N + c0;
            size_t o1 = o0 + (size_t)8 * N;
            float2 v0, v1;
            if (FIN) {
                float sb0 = sB[c0], sb1 = sB[c0 + 1];
                float2 p0 = *(const float2*)(C0 + o0);
                float2 p1 = *(const float2*)(C0 + o1);
                v0.x = (p0.x + (float)acc[i][j][0] * inv128) * sa0 * sb0;
                v0.y = (p0.y + (float)acc[i][j][1] * inv128) * sa0 * sb1;
                v1.x = (p1.x + (float)acc[i][j][2] * inv128) * sa1 * sb0;
                v1.y = (p1.y + (float)acc[i][j][3] * inv128) * sa1 * sb1;
                if (RES) {
                    float2 ra = *(const float2*)(R + o0);
                    float2 rb = *(const float2*)(R + o1);
                    v0.x += ra.x; v0.y += ra.y; v1.x += rb.x; v1.y += rb.y;
                }
            } else {
                v0.x = (float)acc[i][j][0]; v0.y = (float)acc[i][j][1];
                v1.x = (float)acc[i][j][2]; v1.y = (float)acc[i][j][3];
            }
            *(float2*)(C + o0) = v0;
            *(float2*)(C + o1) = v1;
        }
    }
}

// ---------------- RoPE on qkv slab ----------------
__global__ void rope_kernel(float* __restrict__ x, int nheads, int off) {
    int idx = blockIdx.x * 256 + threadIdx.x;
    int i  = idx & 31;
    int hh = (idx >> 5) % nheads;
    int t  = idx / (32 * nheads);
    int s  = t & (SEQ - 1);
    float c  = g_cos[s * 32 + i];
    float sn = g_sin[s * 32 + i];
    float* p = x + (size_t)t * 1536 + off + hh * HDIM;
    float x1 = p[i], x2 = p[i + 32];
    p[i]      = x1 * c - x2 * sn;
    p[i + 32] = x2 * c + x1 * sn;
}

// ---------------- causal GQA flash attention (f32 out) ----------------
__global__ __launch_bounds__(64) void attn_kernel(const float* __restrict__ qkv) {
    __shared__ float Ks[64][64];
    __shared__ float Vs[64][64];
    __shared__ float Ss[64][64];
    int qt = blockIdx.x, h = blockIdx.y, b = blockIdx.z;
    int g = h >> 2;
    int tid = threadIdx.x;
    int qi = qt * 64 + tid;

    const float* qp = qkv + (size_t)(b * SEQ + qi) * 1536 + h * HDIM;
    float qr[64];
    #pragma unroll
    for (int d = 0; d < 64; d += 4) {
        float4 t4 = *(const float4*)(qp + d);
        qr[d] = t4.x * 0.125f; qr[d + 1] = t4.y * 0.125f;
        qr[d + 2] = t4.z * 0.125f; qr[d + 3] = t4.w * 0.125f;
    }
    float m = -1e30f, l = 0.f;
    float acc[64];
    #pragma unroll
    for (int d = 0; d < 64; d++) acc[d] = 0.f;

    for (int j = 0; j <= qt; j++) {
        const float* kp = qkv + (size_t)(b * SEQ + j * 64) * 1536 + 1024 + g * HDIM;
        const float* vp = kp + 256;
        __syncthreads();
        #pragma unroll
        for (int i = 0; i < 16; i++) {
            int idx = i * 64 + tid;
            int r = idx >> 4, c = (idx & 15) * 4;
            *(float4*)&Ks[r][c] = *(const float4*)(kp + (size_t)r * 1536 + c);
            *(float4*)&Vs[r][c] = *(const float4*)(vp + (size_t)r * 1536 + c);
        }
        __syncthreads();
        #pragma unroll
        for (int kk = 0; kk < 64; kk++) {
            float s = 0.f;
            #pragma unroll
            for (int d = 0; d < 64; d += 4) {
                float4 kv = *(const float4*)&Ks[kk][d];
                s += qr[d] * kv.x + qr[d + 1] * kv.y + qr[d + 2] * kv.z + qr[d + 3] * kv.w;
            }
            Ss[kk][tid] = s;
        }
        if (j == qt) {
            for (int kk = tid + 1; kk < 64; kk++) Ss[kk][tid] = -1e30f;
        }
        float tmax = -1e30f;
        #pragma unroll
        for (int kk = 0; kk < 64; kk++) tmax = fmaxf(tmax, Ss[kk][tid]);
        float nm = fmaxf(m, tmax);
        float corr = __expf(m - nm);
        l *= corr;
        #pragma unroll
        for (int d = 0; d < 64; d++) acc[d] *= corr;
        #pragma unroll
        for (int kk = 0; kk < 64; kk++) {
            float p = __expf(Ss[kk][tid] - nm);
            l += p;
            #pragma unroll
            for (int d = 0; d < 64; d += 4) {
                float4 vv = *(const float4*)&Vs[kk][d];
                acc[d]     += p * vv.x; acc[d + 1] += p * vv.y;
                acc[d + 2] += p * vv.z; acc[d + 3] += p * vv.w;
            }
        }
        m = nm;
    }
    float inv = 1.f / l;
    float* op = g_att + (size_t)(b * SEQ + qi) * DIM + h * HDIM;
    #pragma unroll
    for (int d = 0; d < 64; d += 4)
        *(float4*)(op + d) = make_float4(acc[d] * inv, acc[d + 1] * inv,
                                         acc[d + 2] * inv, acc[d + 3] * inv);
}

// ---------------- host orchestration ----------------
extern "C" void kernel_launch(void* const* d_in, const int* in_sizes, int n_in,
                              void* d_out, int out_size) {
    const int*   ids = (const int*)d_in[0];
    const float* emb = (const float*)d_in[1];
    const float* wq  = (const float*)d_in[2];
    const float* wk  = (const float*)d_in[3];
    const float* wv  = (const float*)d_in[4];
    const float* wo  = (const float*)d_in[5];
    const float* n1  = (const float*)d_in[6];
    const float* n2  = (const float*)d_in[7];
    const float* w1  = (const float*)d_in[8];
    const float* w2  = (const float*)d_in[9];
    const float* w3  = (const float*)d_in[10];
    const float* fnw = (const float*)d_in[11];
    float* out = (float*)d_out;

    static int init_done = 0;
    if (!init_done) {
        cudaFuncSetAttribute(gemm_i8<0,0>, cudaFuncAttributeMaxDynamicSharedMemorySize, SMEM_DYN);
        cudaFuncSetAttribute(gemm_i8<0,1>, cudaFuncAttributeMaxDynamicSharedMemorySize, SMEM_DYN);
        cudaFuncSetAttribute(gemm_i8<1,1>, cudaFuncAttributeMaxDynamicSharedMemorySize, SMEM_DYN);
        init_done = 1;
    }

    float *h, *qkv, *att, *f13;
    int8_t *qx, *qatt, *qf1, *qwqkv, *qwo, *qw13, *qw2, *qemb;
    float *sx, *satt, *sf1, *swqkv, *swo, *sw13, *sw2, *semb;
    cudaGetSymbolAddress((void**)&h,     g_h);
    cudaGetSymbolAddress((void**)&qkv,   g_qkv);
    cudaGetSymbolAddress((void**)&att,   g_att);
    cudaGetSymbolAddress((void**)&f13,   g_f13);
    cudaGetSymbolAddress((void**)&qx,    q_x);
    cudaGetSymbolAddress((void**)&qatt,  q_att);
    cudaGetSymbolAddress((void**)&qf1,   q_f1);
    cudaGetSymbolAddress((void**)&qwqkv, q_wqkv);
    cudaGetSymbolAddress((void**)&qwo,   q_wo);
    cudaGetSymbolAddress((void**)&qw13,  q_w13);
    cudaGetSymbolAddress((void**)&qw2,   q_w2);
    cudaGetSymbolAddress((void**)&qemb,  q_emb);
    cudaGetSymbolAddress((void**)&sx,    s_x);
    cudaGetSymbolAddress((void**)&satt,  s_att);
    cudaGetSymbolAddress((void**)&sf1,   s_f1);
    cudaGetSymbolAddress((void**)&swqkv, s_wqkv);
    cudaGetSymbolAddress((void**)&swo,   s_wo);
    cudaGetSymbolAddress((void**)&sw13,  s_w13);
    cudaGetSymbolAddress((void**)&sw2,   s_w2);
    cudaGetSymbolAddress((void**)&semb,  s_emb);

    // ---- quantize all weights (B-side layout [b0|b1|b0], per-row scale) ----
    quant_row_kernel<1><<<NLAYER * 1024, 256>>>(wq, 1024, qwqkv, swqkv, 1024, (size_t)1536 * 3072, 0,    1536);
    quant_row_kernel<1><<<NLAYER * 256,  256>>>(wk, 1024, qwqkv, swqkv, 256,  (size_t)1536 * 3072, 1024, 1536);
    quant_row_kernel<1><<<NLAYER * 256,  256>>>(wv, 1024, qwqkv, swqkv, 256,  (size_t)1536 * 3072, 1280, 1536);
    quant_row_kernel<1><<<NLAYER * 1024, 256>>>(wo, 1024, qwo,   swo,   1024, (size_t)1024 * 3072, 0,    1024);
    quant_row_kernel<1><<<NLAYER * 4096, 256>>>(w1, 1024, qw13,  sw13,  4096, (size_t)8192 * 3072, 0,    8192);
    quant_row_kernel<1><<<NLAYER * 4096, 256>>>(w3, 1024, qw13,  sw13,  4096, (size_t)8192 * 3072, 4096, 8192);
    quant_row_kernel<1><<<NLAYER * 1024, 256>>>(w2, 4096, qw2,   sw2,   1024, (size_t)1024 * 12288, 0,   1024);
    quant_row_kernel<1><<<VOCAB,         256>>>(emb, 1024, qemb, semb,  VOCAB, 0, 0, VOCAB);

    rope_init_kernel<<<SEQ, 32>>>();
    embed_kernel<<<TOK, 256>>>(ids, emb);

    for (int l = 0; l < NLAYER; l++) {
        const int8_t* wqkv_l = qwqkv + (size_t)l * 1536 * 3072;
        const int8_t* wo_l   = qwo   + (size_t)l * 1024 * 3072;
        const int8_t* w13_l  = qw13  + (size_t)l * 8192 * 3072;
        const int8_t* w2_l   = qw2   + (size_t)l * 1024 * 12288;
        const float*  swqkv_l = swqkv + (size_t)l * 1536;
        const float*  swo_l   = swo   + (size_t)l * 1024;
        const float*  sw13_l  = sw13  + (size_t)l * 8192;
        const float*  sw2_l   = sw2   + (size_t)l * 1024;

        rmsnorm_quant_kernel<<<TOK, 256>>>(h, n1 + (size_t)l * DIM, qx, sx);
        // qkv: call1 raw -> qkv slab, call2 finalize in place
        gemm_i8<0,0><<<dim3(1536 / BN, TOK / BM), 256, SMEM_DYN>>>(
            qx, wqkv_l, nullptr, nullptr, qkv, nullptr, nullptr, 1536, 1024, 3072, 3072);
        gemm_i8<0,1><<<dim3(1536 / BN, TOK / BM), 256, SMEM_DYN>>>(
            qx + 1024, wqkv_l + 1024, qkv, nullptr, qkv, sx, swqkv_l, 1536, 2048, 3072, 3072);
        rope_kernel<<<(TOK * NHEAD * 32) / 256, 256>>>(qkv, NHEAD, 0);
        rope_kernel<<<(TOK * KVHEAD * 32) / 256, 256>>>(qkv, KVHEAD, 1024);
        attn_kernel<<<dim3(SEQ / 64, NHEAD, BATCH), 64>>>(qkv);
        quant_row_kernel<0><<<TOK, 256>>>(att, 1024, qatt, satt, TOK, 0, 0, TOK);
        // wo: call1 raw -> qkv (staging), call2 finalize + residual -> h
        gemm_i8<0,0><<<dim3(1024 / BN, TOK / BM), 256, SMEM_DYN>>>(
            qatt, wo_l, nullptr, nullptr, qkv, nullptr, nullptr, 1024, 1024, 3072, 3072);
        gemm_i8<1,1><<<dim3(1024 / BN, TOK / BM), 256, SMEM_DYN>>>(
            qatt + 1024, wo_l + 1024, qkv, h, h, satt, swo_l, 1024, 2048, 3072, 3072);
        rmsnorm_quant_kernel<<<TOK, 256>>>(h, n2 + (size_t)l * DIM, qx, sx);
        // w13: call1 raw -> f13, call2 finalize in place
        gemm_i8<0,0><<<dim3(8192 / BN, TOK / BM), 256, SMEM_DYN>>>(
            qx, w13_l, nullptr, nullptr, f13, nullptr, nullptr, 8192, 1024, 3072, 3072);
        gemm_i8<0,1><<<dim3(8192 / BN, TOK / BM), 256, SMEM_DYN>>>(
            qx + 1024, w13_l + 1024, f13, nullptr, f13, sx, sw13_l, 8192, 2048, 3072, 3072);
        swiglu_quant_kernel<<<TOK, 256>>>();
        // w2: call1 raw -> qkv (staging), call2 finalize + residual -> h
        gemm_i8<0,0><<<dim3(1024 / BN, TOK / BM), 256, SMEM_DYN>>>(
            qf1, w2_l, nullptr, nullptr, qkv, nullptr, nullptr, 1024, 4096, 12288, 12288);
        gemm_i8<1,1><<<dim3(1024 / BN, TOK / BM), 256, SMEM_DYN>>>(
            qf1 + 4096, w2_l + 4096, qkv, h, h, sf1, sw2_l, 1024, 8192, 12288, 12288);
    }
    rmsnorm_quant_kernel<<<TOK, 256>>>(h, fnw, qx, sx);
    gemm_i8<0,0><<<dim3(VOCAB / BN, TOK / BM), 256, SMEM_DYN>>>(
        qx, qemb, nullptr, nullptr, out, nullptr, nullptr, VOCAB, 1024, 3072, 3072);
    gemm_i8<0,1><<<dim3(VOCAB / BN, TOK / BM), 256, SMEM_DYN>>>(
        qx + 1024, qemb + 1024, out, nullptr, out, sx, semb, VOCAB, 2048, 3072, 3072);
}

// round 13
// speedup vs baseline: 1.9405x; 1.9405x over previous
#include <cuda_runtime.h>
#include <cuda_bf16.h>
#include <cuda_fp16.h>
#include <math.h>
#include <stdint.h>

#define SEQ    2048
#define BATCH  2
#define TOK    4096
#define DIM    1024
#define NHEAD  16
#define KVHEAD 4
#define HDIM   64
#define NLAYER 8
#define FF     4096
#define VOCAB  32000

typedef __nv_bfloat16 bf16;

// ---------------- scratch ----------------
__device__ float g_h   [TOK * DIM];
__device__ float g_qkv [TOK * 1536];          // [q(1024)|k(256)|v(256)]
__device__ float g_f13 [TOK * 8192];          // [f1(4096)|f3(4096)]
__device__ float g_cos [SEQ * 32];
__device__ float g_sin [SEQ * 32];
// bf16 3K expanded activations (A: [hi|hi|lo])
__device__ bf16 g_xne [TOK * 3072];           // n1 rmsnorm out (qkv gemm)
__device__ bf16 g_atte[TOK * 3072];           // attention out (wo gemm)
// fp16 2K expanded activations (A: [hi|lo])
__device__ __half g_xnh [TOK * 2048];         // n2/final rmsnorm out
__device__ __half g_f1h [(size_t)TOK * 8192]; // swiglu out (w2 gemm)
// bf16 3K expanded weights (B: [hi|lo|hi])
__device__ bf16 e_wqkv[(size_t)NLAYER * 1536 * 3072];
__device__ bf16 e_wo  [(size_t)NLAYER * 1024 * 3072];
// fp16 2K expanded weights (B: [hi|hi])
__device__ __half e_w13h[(size_t)NLAYER * 8192 * 2048];
__device__ __half e_w2h [(size_t)NLAYER * 1024 * 8192];
__device__ __half e_embh[(size_t)VOCAB * 2048];

__device__ __forceinline__ void split2(float x, bf16& hi, bf16& lo) {
    hi = __float2bfloat16_rn(x);
    lo = __float2bfloat16_rn(x - __bfloat162float(hi));
}
__device__ __forceinline__ void split2h(float x, __half& hi, __half& lo) {
    hi = __float2half_rn(x);
    lo = __float2half_rn(x - __half2float(hi));
}

// ------- bf16 weight expansion, 8 elems/thread: rows = [hi | lo | hi] -------
__global__ void expand_w_kernel(const float* __restrict__ in, bf16* __restrict__ out,
                                int K, int rows_pl, size_t lstride, int row_off) {
    size_t idx = ((size_t)blockIdx.x * 256 + threadIdx.x) * 8;
    size_t rt = idx / K;
    int k  = (int)(idx % K);
    int l  = (int)(rt / rows_pl);
    int r  = (int)(rt % rows_pl);
    float4 x0 = *(const float4*)(in + idx);
    float4 x1 = *(const float4*)(in + idx + 4);
    float xs[8] = {x0.x, x0.y, x0.z, x0.w, x1.x, x1.y, x1.z, x1.w};
    bf16 hi[8], lo[8];
    #pragma unroll
    for (int i = 0; i < 8; i++) split2(xs[i], hi[i], lo[i]);
    bf16* o = out + (size_t)l * lstride + (size_t)(row_off + r) * (3 * K);
    *(uint4*)(o + k)         = *(uint4*)hi;
    *(uint4*)(o + K + k)     = *(uint4*)lo;
    *(uint4*)(o + 2 * K + k) = *(uint4*)hi;
}

// ------- fp16 weight expansion, 8 elems/thread: rows = [hi | hi] (2K) -------
__global__ void expand_w_f16_kernel(const float* __restrict__ in, __half* __restrict__ out,
                                    int K, int rows_pl, size_t lstride, int row_off) {
    size_t idx = ((size_t)blockIdx.x * 256 + threadIdx.x) * 8;
    size_t rt = idx / K;
    int k  = (int)(idx % K);
    int l  = (int)(rt / rows_pl);
    int r  = (int)(rt % rows_pl);
    float4 x0 = *(const float4*)(in + idx);
    float4 x1 = *(const float4*)(in + idx + 4);
    float xs[8] = {x0.x, x0.y, x0.z, x0.w, x1.x, x1.y, x1.z, x1.w};
    __half hi[8];
    #pragma unroll
    for (int i = 0; i < 8; i++) hi[i] = __float2half_rn(xs[i]);
    __half* o = out + (size_t)l * lstride + (size_t)(row_off + r) * (2 * K);
    *(uint4*)(o + k)     = *(uint4*)hi;
    *(uint4*)(o + K + k) = *(uint4*)hi;
}

// ---------------- RoPE tables ----------------
__global__ void rope_init_kernel() {
    int t = blockIdx.x, j = threadIdx.x;
    double inv   = pow(10000.0, -(2.0 * j) / 64.0);
    double r     = 81920.0 * inv / (2.0 * M_PI);
    double gamma = (r - 1.0) / 31.0;
    gamma = gamma < 0.0 ? 0.0 : (gamma > 1.0 ? 1.0 : gamma);
    double inv2  = inv * ((1.0 - gamma) / 40.0 + gamma);
    double c     = sqrt(0.1 * log(40.0) + 1.0);
    double ang   = (double)t * inv2 / c;
    g_cos[t * 32 + j] = (float)cos(ang);
    g_sin[t * 32 + j] = (float)sin(ang);
}

__global__ void embed_kernel(const int* __restrict__ ids, const float* __restrict__ emb) {
    int t = blockIdx.x;
    const float* src = emb + (size_t)ids[t] * DIM;
    float* dst = g_h + (size_t)t * DIM;
    for (int d = threadIdx.x; d < DIM; d += blockDim.x) dst[d] = src[d];
}

// ---------------- shared rmsnorm prologue ----------------
__device__ __forceinline__ float rms_scale(const float* xr, int tid) {
    float s = 0.f;
    #pragma unroll
    for (int i = 0; i < 4; i++) { float v = xr[tid + i * 256]; s += v * v; }
    #pragma unroll
    for (int off = 16; off; off >>= 1) s += __shfl_xor_sync(0xffffffffu, s, off);
    __shared__ float red[8]; __shared__ float rsv;
    if ((tid & 31) == 0) red[tid >> 5] = s;
    __syncthreads();
    if (tid == 0) {
        float t = 0.f;
        #pragma unroll
        for (int i = 0; i < 8; i++) t += red[i];
        rsv = rsqrtf(t / (float)DIM + 1e-6f);
    }
    __syncthreads();
    return rsv;
}

// ---------------- rmsnorm -> bf16 3K [hi|hi|lo] ----------------
__global__ __launch_bounds__(256) void rmsnorm_expand_kernel(
    const float* __restrict__ x, const float* __restrict__ w, bf16* __restrict__ o) {
    int row = blockIdx.x, tid = threadIdx.x;
    const float* xr = x + (size_t)row * DIM;
    float rs = rms_scale(xr, tid);
    bf16* orow = o + (size_t)row * 3072;
    #pragma unroll
    for (int i = 0; i < 2; i++) {
        int d = 2 * (tid + i * 256);
        float2 xv = *(const float2*)(xr + d);
        float2 wv = *(const float2*)(w + d);
        float y0 = xv.x * rs * wv.x, y1 = xv.y * rs * wv.y;
        bf16 h0, l0, h1, l1;
        split2(y0, h0, l0); split2(y1, h1, l1);
        *(__nv_bfloat162*)(orow + d)        = __nv_bfloat162(h0, h1);
        *(__nv_bfloat162*)(orow + 1024 + d) = __nv_bfloat162(h0, h1);
        *(__nv_bfloat162*)(orow + 2048 + d) = __nv_bfloat162(l0, l1);
    }
}

// ---------------- rmsnorm -> fp16 2K [hi|lo] ----------------
__global__ __launch_bounds__(256) void rmsnorm_expand_f16_kernel(
    const float* __restrict__ x, const float* __restrict__ w, __half* __restrict__ o) {
    int row = blockIdx.x, tid = threadIdx.x;
    const float* xr = x + (size_t)row * DIM;
    float rs = rms_scale(xr, tid);
    __half* orow = o + (size_t)row * 2048;
    #pragma unroll
    for (int i = 0; i < 2; i++) {
        int d = 2 * (tid + i * 256);
        float2 xv = *(const float2*)(xr + d);
        float2 wv = *(const float2*)(w + d);
        float y0 = xv.x * rs * wv.x, y1 = xv.y * rs * wv.y;
        __half h0, l0, h1, l1;
        split2h(y0, h0, l0); split2h(y1, h1, l1);
        *(__half2*)(orow + d)        = __half2(h0, h1);
        *(__half2*)(orow + 1024 + d) = __half2(l0, l1);
    }
}

// ================= b16 tensor-core GEMM (BK=64, bf16 or fp16) =================
// C[M,N](f32) = A[M,K'](b16) @ W[N,K'](b16)^T (+R)
// CTA 128x256, 128B SW128 rows, 2-stage cp.async, warp 64x64 = 4x8 m16n8k16.
#define BM 128
#define BN 256
#define BKE 64
#define A_BYTES (BM * BKE * 2)             // 16384
#define B_BYTES (BN * BKE * 2)             // 32768
#define STAGE_BYTES (A_BYTES + B_BYTES)    // 49152
#define SMEM_DYN (2 * STAGE_BYTES)         // 98304

#define CP_ASYNC16(dst, src) \
    asm volatile("cp.async.cg.shared.global [%0], [%1], 16;" :: "r"(dst), "l"(src))
#define CP_COMMIT()  asm volatile("cp.async.commit_group;")
#define CP_WAIT1()   asm volatile("cp.async.wait_group 1;")
#define LDSM_X4(r0, r1, r2, r3, addr) \
    asm volatile("ldmatrix.sync.aligned.m8n8.x4.shared.b16 {%0,%1,%2,%3}, [%4];" \
        : "=r"(r0), "=r"(r1), "=r"(r2), "=r"(r3) : "r"(addr))

template <int FP16>
__device__ __forceinline__ void MMA16(float* c, uint32_t a0, uint32_t a1,
                                      uint32_t a2, uint32_t a3,
                                      uint32_t b0, uint32_t b1) {
    if constexpr (FP16)
        asm volatile("mma.sync.aligned.m16n8k16.row.col.f32.f16.f16.f32 "
            "{%0,%1,%2,%3}, {%4,%5,%6,%7}, {%8,%9}, {%0,%1,%2,%3};"
            : "+f"(c[0]), "+f"(c[1]), "+f"(c[2]), "+f"(c[3])
            : "r"(a0), "r"(a1), "r"(a2), "r"(a3), "r"(b0), "r"(b1));
    else
        asm volatile("mma.sync.aligned.m16n8k16.row.col.f32.bf16.bf16.f32 "
            "{%0,%1,%2,%3}, {%4,%5,%6,%7}, {%8,%9}, {%0,%1,%2,%3};"
            : "+f"(c[0]), "+f"(c[1]), "+f"(c[2]), "+f"(c[3])
            : "r"(a0), "r"(a1), "r"(a2), "r"(a3), "r"(b0), "r"(b1));
}

template <int RES, int FP16>
__global__ __launch_bounds__(256) void gemm_b16(
    const uint16_t* __restrict__ A, const uint16_t* __restrict__ W,
    const float* __restrict__ R, float* __restrict__ C, int N, int K) {
    extern __shared__ __align__(16) char smem[];
    const int tid  = threadIdx.x;
    const int lane = tid & 31;
    const int wid  = tid >> 5;
    const int wm   = wid >> 2;
    const int wn   = wid & 3;
    const int bm   = blockIdx.y * BM;
    const int bn   = blockIdx.x * BN;
    const uint32_t smem_u = (uint32_t)__cvta_generic_to_shared(smem);

    const int lrow = tid >> 3;
    const int lcol = tid & 7;
    const uint16_t* AgBase = A + (size_t)bm * K;
    const uint16_t* WgBase = W + (size_t)bn * K;

    const int flr = lane & 15;
    const int fhi = lane >> 4;
    int aRow[4], aXor[4];
    #pragma unroll
    for (int i = 0; i < 4; i++) { aRow[i] = wm * 64 + i * 16 + flr; aXor[i] = aRow[i] & 7; }
    const int bkf = (lane >> 3) & 1;
    int bRow[4], bXor[4];
    #pragma unroll
    for (int p = 0; p < 4; p++) {
        bRow[p] = wn * 64 + (lane & 7) + fhi * 8 + p * 16;
        bXor[p] = bRow[p] & 7;
    }

    float acc[4][8][4];
    #pragma unroll
    for (int i = 0; i < 4; i++)
        #pragma unroll
        for (int j = 0; j < 8; j++)
            #pragma unroll
            for (int q = 0; q < 4; q++) acc[i][j][q] = 0.f;

    const int nk = K / BKE;

    auto load_stage = [&](int kt) {
        uint32_t base = smem_u + (kt & 1) * STAGE_BYTES;
        int k0 = kt * BKE;
        #pragma unroll
        for (int it = 0; it < 4; it++) {
            int r = lrow + it * 32;
            uint32_t dst = base + r * 128 + ((lcol ^ (r & 7)) << 4);
            CP_ASYNC16(dst, AgBase + (size_t)r * K + k0 + lcol * 8);
        }
        uint32_t bb = base + A_BYTES;
        #pragma unroll
        for (int it = 0; it < 8; it++) {
            int r = lrow + it * 32;
            uint32_t dst = bb + r * 128 + ((lcol ^ (r & 7)) << 4);
            CP_ASYNC16(dst, WgBase + (size_t)r * K + k0 + lcol * 8);
        }
    };

    load_stage(0);
    CP_COMMIT();

    for (int kt = 0; kt < nk; kt++) {
        if (kt + 1 < nk) load_stage(kt + 1);
        CP_COMMIT();
        CP_WAIT1();
        __syncthreads();

        uint32_t cbase = smem_u + (kt & 1) * STAGE_BYTES;
        #pragma unroll
        for (int s = 0; s < 4; s++) {
            uint32_t af[4][4];
            #pragma unroll
            for (int i = 0; i < 4; i++) {
                uint32_t addr = cbase + aRow[i] * 128 + (((2 * s + fhi) ^ aXor[i]) << 4);
                LDSM_X4(af[i][0], af[i][1], af[i][2], af[i][3], addr);
            }
            #pragma unroll
            for (int p = 0; p < 4; p++) {
                uint32_t addr = cbase + (uint32_t)A_BYTES + bRow[p] * 128 +
                                (((2 * s + bkf) ^ bXor[p]) << 4);
                uint32_t b0, b1, b2, b3;
                LDSM_X4(b0, b1, b2, b3, addr);
                #pragma unroll
                for (int i = 0; i < 4; i++) {
                    MMA16<FP16>(acc[i][2 * p],     af[i][0], af[i][1], af[i][2], af[i][3], b0, b1);
                    MMA16<FP16>(acc[i][2 * p + 1], af[i][0], af[i][1], af[i][2], af[i][3], b2, b3);
                }
            }
        }
        __syncthreads();
    }

    const int gid = lane >> 2, tig = lane & 3;
    #pragma unroll
    for (int i = 0; i < 4; i++) {
        int r0 = bm + wm * 64 + i * 16 + gid;
        #pragma unroll
        for (int j = 0; j < 8; j++) {
            int c0 = bn + wn * 64 + j * 8 + tig * 2;
            size_t o0 = (size_t)r0 * N + c0;
            size_t o1 = o0 + (size_t)8 * N;
            float2 v0 = make_float2(acc[i][j][0], acc[i][j][1]);
            float2 v1 = make_float2(acc[i][j][2], acc[i][j][3]);
            if (RES) {
                float2 ra = *(const float2*)(R + o0);
                float2 rb = *(const float2*)(R + o1);
                v0.x += ra.x; v0.y += ra.y; v1.x += rb.x; v1.y += rb.y;
            }
            *(float2*)(C + o0) = v0;
            *(float2*)(C + o1) = v1;
        }
    }
}

// ---------------- RoPE on qkv slab ----------------
__global__ void rope_kernel(float* __restrict__ x, int nheads, int off) {
    int idx = blockIdx.x * 256 + threadIdx.x;
    int i  = idx & 31;
    int hh = (idx >> 5) % nheads;
    int t  = idx / (32 * nheads);
    int s  = t & (SEQ - 1);
    float c  = g_cos[s * 32 + i];
    float sn = g_sin[s * 32 + i];
    float* p = x + (size_t)t * 1536 + off + hh * HDIM;
    float x1 = p[i], x2 = p[i + 32];
    p[i]      = x1 * c - x2 * sn;
    p[i + 32] = x2 * c + x1 * sn;
}

// ---------------- causal GQA flash attention (thread-per-query) ---------
__global__ __launch_bounds__(64) void attn_kernel(
    const float* __restrict__ qkv, bf16* __restrict__ oe) {
    __shared__ float Ks[64][64];
    __shared__ float Vs[64][64];
    __shared__ float Ss[64][64];
    int qt = blockIdx.x, h = blockIdx.y, b = blockIdx.z;
    int g = h >> 2;
    int tid = threadIdx.x;
    int qi = qt * 64 + tid;

    const float* qp = qkv + (size_t)(b * SEQ + qi) * 1536 + h * HDIM;
    float qr[64];
    #pragma unroll
    for (int d = 0; d < 64; d += 4) {
        float4 t4 = *(const float4*)(qp + d);
        qr[d] = t4.x * 0.125f; qr[d + 1] = t4.y * 0.125f;
        qr[d + 2] = t4.z * 0.125f; qr[d + 3] = t4.w * 0.125f;
    }
    float m = -1e30f, l = 0.f;
    float acc[64];
    #pragma unroll
    for (int d = 0; d < 64; d++) acc[d] = 0.f;

    for (int j = 0; j <= qt; j++) {
        const float* kp = qkv + (size_t)(b * SEQ + j * 64) * 1536 + 1024 + g * HDIM;
        const float* vp = kp + 256;
        __syncthreads();
        #pragma unroll
        for (int i = 0; i < 16; i++) {
            int idx = i * 64 + tid;
            int r = idx >> 4, c = (idx & 15) * 4;
            *(float4*)&Ks[r][c] = *(const float4*)(kp + (size_t)r * 1536 + c);
            *(float4*)&Vs[r][c] = *(const float4*)(vp + (size_t)r * 1536 + c);
        }
        __syncthreads();
        #pragma unroll
        for (int kk = 0; kk < 64; kk++) {
            float s = 0.f;
            #pragma unroll
            for (int d = 0; d < 64; d += 4) {
                float4 kv = *(const float4*)&Ks[kk][d];
                s += qr[d] * kv.x + qr[d + 1] * kv.y + qr[d + 2] * kv.z + qr[d + 3] * kv.w;
            }
            Ss[kk][tid] = s;
        }
        if (j == qt) {
            for (int kk = tid + 1; kk < 64; kk++) Ss[kk][tid] = -1e30f;
        }
        float tmax = -1e30f;
        #pragma unroll
        for (int kk = 0; kk < 64; kk++) tmax = fmaxf(tmax, Ss[kk][tid]);
        float nm = fmaxf(m, tmax);
        float corr = __expf(m - nm);
        l *= corr;
        #pragma unroll
        for (int d = 0; d < 64; d++) acc[d] *= corr;
        #pragma unroll
        for (int kk = 0; kk < 64; kk++) {
            float p = __expf(Ss[kk][tid] - nm);
            l += p;
            #pragma unroll
            for (int d = 0; d < 64; d += 4) {
                float4 vv = *(const float4*)&Vs[kk][d];
                acc[d]     += p * vv.x; acc[d + 1] += p * vv.y;
                acc[d + 2] += p * vv.z; acc[d + 3] += p * vv.w;
            }
        }
        m = nm;
    }
    float inv = 1.f / l;
    bf16* op = oe + (size_t)(b * SEQ + qi) * 3072 + h * HDIM;
    #pragma unroll
    for (int d = 0; d < 64; d += 2) {
        float y0 = acc[d] * inv, y1 = acc[d + 1] * inv;
        bf16 h0, l0, h1, l1;
        split2(y0, h0, l0); split2(y1, h1, l1);
        *(__nv_bfloat162*)(op + d)        = __nv_bfloat162(h0, h1);
        *(__nv_bfloat162*)(op + 1024 + d) = __nv_bfloat162(h0, h1);
        *(__nv_bfloat162*)(op + 2048 + d) = __nv_bfloat162(l0, l1);
    }
}

// ---------------- SwiGLU -> fp16 2K [hi|lo], 4 elems/thread ----------------
__global__ void swiglu_expand_f16_kernel() {
    int i4 = (blockIdx.x * 256 + threadIdx.x) * 4;   // over TOK*FF
    int t = i4 >> 12, c = i4 & 4095;
    float4 a4 = *(const float4*)(g_f13 + (size_t)t * 8192 + c);
    float4 b4 = *(const float4*)(g_f13 + (size_t)t * 8192 + 4096 + c);
    float as[4] = {a4.x, a4.y, a4.z, a4.w};
    float bs[4] = {b4.x, b4.y, b4.z, b4.w};
    __half hi[4], lo[4];
    #pragma unroll
    for (int i = 0; i < 4; i++) {
        float u = (as[i] / (1.f + __expf(-as[i]))) * bs[i];
        split2h(u, hi[i], lo[i]);
    }
    __half* o = g_f1h + (size_t)t * 8192;
    *(uint2*)(o + c)        = *(uint2*)hi;
    *(uint2*)(o + 4096 + c) = *(uint2*)lo;
}

// ---------------- host orchestration ----------------
extern "C" void kernel_launch(void* const* d_in, const int* in_sizes, int n_in,
                              void* d_out, int out_size) {
    const int*   ids = (const int*)d_in[0];
    const float* emb = (const float*)d_in[1];
    const float* wq  = (const float*)d_in[2];
    const float* wk  = (const float*)d_in[3];
    const float* wv  = (const float*)d_in[4];
    const float* wo  = (const float*)d_in[5];
    const float* n1  = (const float*)d_in[6];
    const float* n2  = (const float*)d_in[7];
    const float* w1  = (const float*)d_in[8];
    const float* w2  = (const float*)d_in[9];
    const float* w3  = (const float*)d_in[10];
    const float* fnw = (const float*)d_in[11];
    float* out = (float*)d_out;

    static int smem_set = 0;
    if (!smem_set) {
        cudaFuncSetAttribute(gemm_b16<0,0>, cudaFuncAttributeMaxDynamicSharedMemorySize, SMEM_DYN);
        cudaFuncSetAttribute(gemm_b16<1,0>, cudaFuncAttributeMaxDynamicSharedMemorySize, SMEM_DYN);
        cudaFuncSetAttribute(gemm_b16<0,1>, cudaFuncAttributeMaxDynamicSharedMemorySize, SMEM_DYN);
        cudaFuncSetAttribute(gemm_b16<1,1>, cudaFuncAttributeMaxDynamicSharedMemorySize, SMEM_DYN);
        smem_set = 1;
    }

    float *h, *qkv, *f13;
    bf16 *xne, *atte, *ewqkv, *ewo;
    __half *xnh, *f1h, *ew13h, *ew2h, *eembh;
    cudaGetSymbolAddress((void**)&h,     g_h);
    cudaGetSymbolAddress((void**)&qkv,   g_qkv);
    cudaGetSymbolAddress((void**)&f13,   g_f13);
    cudaGetSymbolAddress((void**)&xne,   g_xne);
    cudaGetSymbolAddress((void**)&atte,  g_atte);
    cudaGetSymbolAddress((void**)&xnh,   g_xnh);
    cudaGetSymbolAddress((void**)&f1h,   g_f1h);
    cudaGetSymbolAddress((void**)&ewqkv, e_wqkv);
    cudaGetSymbolAddress((void**)&ewo,   e_wo);
    cudaGetSymbolAddress((void**)&ew13h, e_w13h);
    cudaGetSymbolAddress((void**)&ew2h,  e_w2h);
    cudaGetSymbolAddress((void**)&eembh, e_embh);

    // ---- expand weights: bf16 3K for qkv/wo, fp16 2K for w13/w2/emb ----
    expand_w_kernel<<<(NLAYER * 1024 * 1024) / 2048, 256>>>(wq, ewqkv, 1024, 1024, (size_t)1536 * 3072, 0);
    expand_w_kernel<<<(NLAYER * 256  * 1024) / 2048, 256>>>(wk, ewqkv, 1024, 256,  (size_t)1536 * 3072, 1024);
    expand_w_kernel<<<(NLAYER * 256  * 1024) / 2048, 256>>>(wv, ewqkv, 1024, 256,  (size_t)1536 * 3072, 1280);
    expand_w_kernel<<<(NLAYER * 1024 * 1024) / 2048, 256>>>(wo, ewo,   1024, 1024, (size_t)1024 * 3072, 0);
    expand_w_f16_kernel<<<(NLAYER * 4096 * 1024) / 2048, 256>>>(w1, ew13h, 1024, 4096, (size_t)8192 * 2048, 0);
    expand_w_f16_kernel<<<(NLAYER * 4096 * 1024) / 2048, 256>>>(w3, ew13h, 1024, 4096, (size_t)8192 * 2048, 4096);
    expand_w_f16_kernel<<<(NLAYER * 1024 * 4096) / 2048, 256>>>(w2, ew2h,  4096, 1024, (size_t)1024 * 8192, 0);
    expand_w_f16_kernel<<<(VOCAB * 1024) / 2048, 256>>>(emb, eembh, 1024, VOCAB, 0, 0);

    rope_init_kernel<<<SEQ, 32>>>();
    embed_kernel<<<TOK, 256>>>(ids, emb);

    for (int l = 0; l < NLAYER; l++) {
        // --- attention block: bf16 3K (proven 4.1e-5 path) ---
        rmsnorm_expand_kernel<<<TOK, 256>>>(h, n1 + (size_t)l * DIM, xne);
        gemm_b16<0,0><<<dim3(1536 / BN, TOK / BM), 256, SMEM_DYN>>>(
            (const uint16_t*)xne, (const uint16_t*)(ewqkv + (size_t)l * 1536 * 3072),
            nullptr, qkv, 1536, 3072);
        rope_kernel<<<(TOK * NHEAD * 32) / 256, 256>>>(qkv, NHEAD, 0);
        rope_kernel<<<(TOK * KVHEAD * 32) / 256, 256>>>(qkv, KVHEAD, 1024);
        attn_kernel<<<dim3(SEQ / 64, NHEAD, BATCH), 64>>>(qkv, atte);
        gemm_b16<1,0><<<dim3(1024 / BN, TOK / BM), 256, SMEM_DYN>>>(
            (const uint16_t*)atte, (const uint16_t*)(ewo + (size_t)l * 1024 * 3072),
            h, h, 1024, 3072);
        // --- FFN block: fp16 2K (one-sided 11-bit error) ---
        rmsnorm_expand_f16_kernel<<<TOK, 256>>>(h, n2 + (size_t)l * DIM, xnh);
        gemm_b16<0,1><<<dim3(8192 / BN, TOK / BM), 256, SMEM_DYN>>>(
            (const uint16_t*)xnh, (const uint16_t*)(ew13h + (size_t)l * 8192 * 2048),
            nullptr, f13, 8192, 2048);
        swiglu_expand_f16_kernel<<<(TOK * FF) / 1024, 256>>>();
        gemm_b16<1,1><<<dim3(1024 / BN, TOK / BM), 256, SMEM_DYN>>>(
            (const uint16_t*)f1h, (const uint16_t*)(ew2h + (size_t)l * 1024 * 8192),
            h, h, 1024, 8192);
    }
    // --- logits: fp16 2K ---
    rmsnorm_expand_f16_kernel<<<TOK, 256>>>(h, fnw, xnh);
    gemm_b16<0,1><<<dim3(VOCAB / BN, TOK / BM), 256, SMEM_DYN>>>(
        (const uint16_t*)xnh, (const uint16_t*)eembh, nullptr, out, VOCAB, 2048);
}

// round 14
// speedup vs baseline: 2.6578x; 1.3696x over previous
#include <cuda_runtime.h>
#include <cuda_bf16.h>
#include <cuda_fp16.h>
#include <math.h>
#include <stdint.h>

#define SEQ    2048
#define BATCH  2
#define TOK    4096
#define DIM    1024
#define NHEAD  16
#define KVHEAD 4
#define HDIM   64
#define NLAYER 8
#define FF     4096
#define VOCAB  32000

typedef __nv_bfloat16 bf16;

// ---------------- scratch ----------------
__device__ float g_h   [TOK * DIM];
__device__ float g_qkv [TOK * 1536];          // [q(1024)|k(256)|v(256)]
__device__ float g_f13 [TOK * 8192];          // [f1(4096)|f3(4096)]
__device__ float g_cos [SEQ * 32];
__device__ float g_sin [SEQ * 32];
// bf16 3K expanded activations (A: [hi|hi|lo])
__device__ bf16 g_xne [TOK * 3072];           // n1 rmsnorm out (qkv gemm)
__device__ bf16 g_atte[TOK * 3072];           // attention out (wo gemm)
// fp16 2K expanded activations (A: [hi|lo])
__device__ __half g_xnh [TOK * 2048];         // n2/final rmsnorm out
__device__ __half g_f1h [(size_t)TOK * 8192]; // swiglu out (w2 gemm)
// bf16 3K expanded weights (B: [hi|lo|hi])
__device__ bf16 e_wqkv[(size_t)NLAYER * 1536 * 3072];
__device__ bf16 e_wo  [(size_t)NLAYER * 1024 * 3072];
// fp16 2K expanded weights (B: [hi|hi])
__device__ __half e_w13h[(size_t)NLAYER * 8192 * 2048];
__device__ __half e_w2h [(size_t)NLAYER * 1024 * 8192];
__device__ __half e_embh[(size_t)VOCAB * 2048];

__device__ __forceinline__ void split2(float x, bf16& hi, bf16& lo) {
    hi = __float2bfloat16_rn(x);
    lo = __float2bfloat16_rn(x - __bfloat162float(hi));
}
__device__ __forceinline__ void split2h(float x, __half& hi, __half& lo) {
    hi = __float2half_rn(x);
    lo = __float2half_rn(x - __half2float(hi));
}

// ---- packed f32x2 helpers (sm_103 Blackwell packed math, PTX-only) ----
#define F32X2_FMA(acc, a, b) \
    asm volatile("fma.rn.f32x2 %0, %1, %2, %0;" : "+l"(acc) : "l"(a), "l"(b))
#define F32X2_MUL(d, a, b) \
    asm volatile("mul.rn.f32x2 %0, %1, %2;" : "=l"(d) : "l"(a), "l"(b))
#define F32X2_ADD(d, a, b) \
    asm volatile("add.rn.f32x2 %0, %1, %2;" : "=l"(d) : "l"(a), "l"(b))
#define PACK2(d, lo, hi) \
    asm("mov.b64 %0, {%1, %2};" : "=l"(d) : "f"(lo), "f"(hi))
#define UNPACK2(lo, hi, d) \
    asm("mov.b64 {%0, %1}, %2;" : "=f"(lo), "=f"(hi) : "l"(d))
#define LDS_V2U64(a, b, addr) \
    asm volatile("ld.shared.v2.u64 {%0, %1}, [%2];" : "=l"(a), "=l"(b) : "r"(addr))

// ------- bf16 weight expansion, 8 elems/thread: rows = [hi | lo | hi] -------
__global__ void expand_w_kernel(const float* __restrict__ in, bf16* __restrict__ out,
                                int K, int rows_pl, size_t lstride, int row_off) {
    size_t idx = ((size_t)blockIdx.x * 256 + threadIdx.x) * 8;
    size_t rt = idx / K;
    int k  = (int)(idx % K);
    int l  = (int)(rt / rows_pl);
    int r  = (int)(rt % rows_pl);
    float4 x0 = *(const float4*)(in + idx);
    float4 x1 = *(const float4*)(in + idx + 4);
    float xs[8] = {x0.x, x0.y, x0.z, x0.w, x1.x, x1.y, x1.z, x1.w};
    bf16 hi[8], lo[8];
    #pragma unroll
    for (int i = 0; i < 8; i++) split2(xs[i], hi[i], lo[i]);
    bf16* o = out + (size_t)l * lstride + (size_t)(row_off + r) * (3 * K);
    *(uint4*)(o + k)         = *(uint4*)hi;
    *(uint4*)(o + K + k)     = *(uint4*)lo;
    *(uint4*)(o + 2 * K + k) = *(uint4*)hi;
}

// ------- fp16 weight expansion, 8 elems/thread: rows = [hi | hi] (2K) -------
__global__ void expand_w_f16_kernel(const float* __restrict__ in, __half* __restrict__ out,
                                    int K, int rows_pl, size_t lstride, int row_off) {
    size_t idx = ((size_t)blockIdx.x * 256 + threadIdx.x) * 8;
    size_t rt = idx / K;
    int k  = (int)(idx % K);
    int l  = (int)(rt / rows_pl);
    int r  = (int)(rt % rows_pl);
    float4 x0 = *(const float4*)(in + idx);
    float4 x1 = *(const float4*)(in + idx + 4);
    float xs[8] = {x0.x, x0.y, x0.z, x0.w, x1.x, x1.y, x1.z, x1.w};
    __half hi[8];
    #pragma unroll
    for (int i = 0; i < 8; i++) hi[i] = __float2half_rn(xs[i]);
    __half* o = out + (size_t)l * lstride + (size_t)(row_off + r) * (2 * K);
    *(uint4*)(o + k)     = *(uint4*)hi;
    *(uint4*)(o + K + k) = *(uint4*)hi;
}

// ---------------- RoPE tables ----------------
__global__ void rope_init_kernel() {
    int t = blockIdx.x, j = threadIdx.x;
    double inv   = pow(10000.0, -(2.0 * j) / 64.0);
    double r     = 81920.0 * inv / (2.0 * M_PI);
    double gamma = (r - 1.0) / 31.0;
    gamma = gamma < 0.0 ? 0.0 : (gamma > 1.0 ? 1.0 : gamma);
    double inv2  = inv * ((1.0 - gamma) / 40.0 + gamma);
    double c     = sqrt(0.1 * log(40.0) + 1.0);
    double ang   = (double)t * inv2 / c;
    g_cos[t * 32 + j] = (float)cos(ang);
    g_sin[t * 32 + j] = (float)sin(ang);
}

__global__ void embed_kernel(const int* __restrict__ ids, const float* __restrict__ emb) {
    int t = blockIdx.x;
    const float* src = emb + (size_t)ids[t] * DIM;
    float* dst = g_h + (size_t)t * DIM;
    for (int d = threadIdx.x; d < DIM; d += blockDim.x) dst[d] = src[d];
}

// ---------------- shared rmsnorm prologue ----------------
__device__ __forceinline__ float rms_scale(const float* xr, int tid) {
    float s = 0.f;
    #pragma unroll
    for (int i = 0; i < 4; i++) { float v = xr[tid + i * 256]; s += v * v; }
    #pragma unroll
    for (int off = 16; off; off >>= 1) s += __shfl_xor_sync(0xffffffffu, s, off);
    __shared__ float red[8]; __shared__ float rsv;
    if ((tid & 31) == 0) red[tid >> 5] = s;
    __syncthreads();
    if (tid == 0) {
        float t = 0.f;
        #pragma unroll
        for (int i = 0; i < 8; i++) t += red[i];
        rsv = rsqrtf(t / (float)DIM + 1e-6f);
    }
    __syncthreads();
    return rsv;
}

// ---------------- rmsnorm -> bf16 3K [hi|hi|lo] ----------------
__global__ __launch_bounds__(256) void rmsnorm_expand_kernel(
    const float* __restrict__ x, const float* __restrict__ w, bf16* __restrict__ o) {
    int row = blockIdx.x, tid = threadIdx.x;
    const float* xr = x + (size_t)row * DIM;
    float rs = rms_scale(xr, tid);
    bf16* orow = o + (size_t)row * 3072;
    #pragma unroll
    for (int i = 0; i < 2; i++) {
        int d = 2 * (tid + i * 256);
        float2 xv = *(const float2*)(xr + d);
        float2 wv = *(const float2*)(w + d);
        float y0 = xv.x * rs * wv.x, y1 = xv.y * rs * wv.y;
        bf16 h0, l0, h1, l1;
        split2(y0, h0, l0); split2(y1, h1, l1);
        *(__nv_bfloat162*)(orow + d)        = __nv_bfloat162(h0, h1);
        *(__nv_bfloat162*)(orow + 1024 + d) = __nv_bfloat162(h0, h1);
        *(__nv_bfloat162*)(orow + 2048 + d) = __nv_bfloat162(l0, l1);
    }
}

// ---------------- rmsnorm -> fp16 2K [hi|lo] ----------------
__global__ __launch_bounds__(256) void rmsnorm_expand_f16_kernel(
    const float* __restrict__ x, const float* __restrict__ w, __half* __restrict__ o) {
    int row = blockIdx.x, tid = threadIdx.x;
    const float* xr = x + (size_t)row * DIM;
    float rs = rms_scale(xr, tid);
    __half* orow = o + (size_t)row * 2048;
    #pragma unroll
    for (int i = 0; i < 2; i++) {
        int d = 2 * (tid + i * 256);
        float2 xv = *(const float2*)(xr + d);
        float2 wv = *(const float2*)(w + d);
        float y0 = xv.x * rs * wv.x, y1 = xv.y * rs * wv.y;
        __half h0, l0, h1, l1;
        split2h(y0, h0, l0); split2h(y1, h1, l1);
        *(__half2*)(orow + d)        = __half2(h0, h1);
        *(__half2*)(orow + 1024 + d) = __half2(l0, l1);
    }
}

// ================= b16 tensor-core GEMM (BK=64, bf16 or fp16) =================
#define BM 128
#define BN 256
#define BKE 64
#define A_BYTES (BM * BKE * 2)             // 16384
#define B_BYTES (BN * BKE * 2)             // 32768
#define STAGE_BYTES (A_BYTES + B_BYTES)    // 49152
#define SMEM_DYN (2 * STAGE_BYTES)         // 98304

#define CP_ASYNC16(dst, src) \
    asm volatile("cp.async.cg.shared.global [%0], [%1], 16;" :: "r"(dst), "l"(src))
#define CP_COMMIT()  asm volatile("cp.async.commit_group;")
#define CP_WAIT1()   asm volatile("cp.async.wait_group 1;")
#define LDSM_X4(r0, r1, r2, r3, addr) \
    asm volatile("ldmatrix.sync.aligned.m8n8.x4.shared.b16 {%0,%1,%2,%3}, [%4];" \
        : "=r"(r0), "=r"(r1), "=r"(r2), "=r"(r3) : "r"(addr))

template <int FP16>
__device__ __forceinline__ void MMA16(float* c, uint32_t a0, uint32_t a1,
                                      uint32_t a2, uint32_t a3,
                                      uint32_t b0, uint32_t b1) {
    if constexpr (FP16)
        asm volatile("mma.sync.aligned.m16n8k16.row.col.f32.f16.f16.f32 "
            "{%0,%1,%2,%3}, {%4,%5,%6,%7}, {%8,%9}, {%0,%1,%2,%3};"
            : "+f"(c[0]), "+f"(c[1]), "+f"(c[2]), "+f"(c[3])
            : "r"(a0), "r"(a1), "r"(a2), "r"(a3), "r"(b0), "r"(b1));
    else
        asm volatile("mma.sync.aligned.m16n8k16.row.col.f32.bf16.bf16.f32 "
            "{%0,%1,%2,%3}, {%4,%5,%6,%7}, {%8,%9}, {%0,%1,%2,%3};"
            : "+f"(c[0]), "+f"(c[1]), "+f"(c[2]), "+f"(c[3])
            : "r"(a0), "r"(a1), "r"(a2), "r"(a3), "r"(b0), "r"(b1));
}

template <int RES, int FP16>
__global__ __launch_bounds__(256) void gemm_b16(
    const uint16_t* __restrict__ A, const uint16_t* __restrict__ W,
    const float* __restrict__ R, float* __restrict__ C, int N, int K) {
    extern __shared__ __align__(16) char smem[];
    const int tid  = threadIdx.x;
    const int lane = tid & 31;
    const int wid  = tid >> 5;
    const int wm   = wid >> 2;
    const int wn   = wid & 3;
    const int bm   = blockIdx.y * BM;
    const int bn   = blockIdx.x * BN;
    const uint32_t smem_u = (uint32_t)__cvta_generic_to_shared(smem);

    const int lrow = tid >> 3;
    const int lcol = tid & 7;
    const uint16_t* AgBase = A + (size_t)bm * K;
    const uint16_t* WgBase = W + (size_t)bn * K;

    const int flr = lane & 15;
    const int fhi = lane >> 4;
    int aRow[4], aXor[4];
    #pragma unroll
    for (int i = 0; i < 4; i++) { aRow[i] = wm * 64 + i * 16 + flr; aXor[i] = aRow[i] & 7; }
    const int bkf = (lane >> 3) & 1;
    int bRow[4], bXor[4];
    #pragma unroll
    for (int p = 0; p < 4; p++) {
        bRow[p] = wn * 64 + (lane & 7) + fhi * 8 + p * 16;
        bXor[p] = bRow[p] & 7;
    }

    float acc[4][8][4];
    #pragma unroll
    for (int i = 0; i < 4; i++)
        #pragma unroll
        for (int j = 0; j < 8; j++)
            #pragma unroll
            for (int q = 0; q < 4; q++) acc[i][j][q] = 0.f;

    const int nk = K / BKE;

    auto load_stage = [&](int kt) {
        uint32_t base = smem_u + (kt & 1) * STAGE_BYTES;
        int k0 = kt * BKE;
        #pragma unroll
        for (int it = 0; it < 4; it++) {
            int r = lrow + it * 32;
            uint32_t dst = base + r * 128 + ((lcol ^ (r & 7)) << 4);
            CP_ASYNC16(dst, AgBase + (size_t)r * K + k0 + lcol * 8);
        }
        uint32_t bb = base + A_BYTES;
        #pragma unroll
        for (int it = 0; it < 8; it++) {
            int r = lrow + it * 32;
            uint32_t dst = bb + r * 128 + ((lcol ^ (r & 7)) << 4);
            CP_ASYNC16(dst, WgBase + (size_t)r * K + k0 + lcol * 8);
        }
    };

    load_stage(0);
    CP_COMMIT();

    for (int kt = 0; kt < nk; kt++) {
        if (kt + 1 < nk) load_stage(kt + 1);
        CP_COMMIT();
        CP_WAIT1();
        __syncthreads();

        uint32_t cbase = smem_u + (kt & 1) * STAGE_BYTES;
        #pragma unroll
        for (int s = 0; s < 4; s++) {
            uint32_t af[4][4];
            #pragma unroll
            for (int i = 0; i < 4; i++) {
                uint32_t addr = cbase + aRow[i] * 128 + (((2 * s + fhi) ^ aXor[i]) << 4);
                LDSM_X4(af[i][0], af[i][1], af[i][2], af[i][3], addr);
            }
            #pragma unroll
            for (int p = 0; p < 4; p++) {
                uint32_t addr = cbase + (uint32_t)A_BYTES + bRow[p] * 128 +
                                (((2 * s + bkf) ^ bXor[p]) << 4);
                uint32_t b0, b1, b2, b3;
                LDSM_X4(b0, b1, b2, b3, addr);
                #pragma unroll
                for (int i = 0; i < 4; i++) {
                    MMA16<FP16>(acc[i][2 * p],     af[i][0], af[i][1], af[i][2], af[i][3], b0, b1);
                    MMA16<FP16>(acc[i][2 * p + 1], af[i][0], af[i][1], af[i][2], af[i][3], b2, b3);
                }
            }
        }
        __syncthreads();
    }

    const int gid = lane >> 2, tig = lane & 3;
    #pragma unroll
    for (int i = 0; i < 4; i++) {
        int r0 = bm + wm * 64 + i * 16 + gid;
        #pragma unroll
        for (int j = 0; j < 8; j++) {
            int c0 = bn + wn * 64 + j * 8 + tig * 2;
            size_t o0 = (size_t)r0 * N + c0;
            size_t o1 = o0 + (size_t)8 * N;
            float2 v0 = make_float2(acc[i][j][0], acc[i][j][1]);
            float2 v1 = make_float2(acc[i][j][2], acc[i][j][3]);
            if (RES) {
                float2 ra = *(const float2*)(R + o0);
                float2 rb = *(const float2*)(R + o1);
                v0.x += ra.x; v0.y += ra.y; v1.x += rb.x; v1.y += rb.y;
            }
            *(float2*)(C + o0) = v0;
            *(float2*)(C + o1) = v1;
        }
    }
}

// ---------------- RoPE on qkv slab ----------------
__global__ void rope_kernel(float* __restrict__ x, int nheads, int off) {
    int idx = blockIdx.x * 256 + threadIdx.x;
    int i  = idx & 31;
    int hh = (idx >> 5) % nheads;
    int t  = idx / (32 * nheads);
    int s  = t & (SEQ - 1);
    float c  = g_cos[s * 32 + i];
    float sn = g_sin[s * 32 + i];
    float* p = x + (size_t)t * 1536 + off + hh * HDIM;
    float x1 = p[i], x2 = p[i + 32];
    p[i]      = x1 * c - x2 * sn;
    p[i + 32] = x2 * c + x1 * sn;
}

// ---------------- causal GQA flash attention, f32x2 packed math ----------
// thread-per-query, 64 thr/block; q/acc held as packed f32x2 pairs;
// K/V read via ld.shared.v2.u64; fma.rn.f32x2 halves FMA count + chains.
__global__ __launch_bounds__(64) void attn_kernel(
    const float* __restrict__ qkv, bf16* __restrict__ oe) {
    __shared__ __align__(16) float Ks[64][64];
    __shared__ __align__(16) float Vs[64][64];
    __shared__ float Ss[64][64];
    int qt = blockIdx.x, h = blockIdx.y, b = blockIdx.z;
    int g = h >> 2;
    int tid = threadIdx.x;
    int qi = qt * 64 + tid;
    const uint32_t ksb = (uint32_t)__cvta_generic_to_shared(&Ks[0][0]);
    const uint32_t vsb = (uint32_t)__cvta_generic_to_shared(&Vs[0][0]);

    // load q (scaled) as 32 packed f32x2
    const float* qp = qkv + (size_t)(b * SEQ + qi) * 1536 + h * HDIM;
    uint64_t q2[32];
    #pragma unroll
    for (int d = 0; d < 64; d += 4) {
        float4 t4 = *(const float4*)(qp + d);
        PACK2(q2[d / 2],     t4.x * 0.125f, t4.y * 0.125f);
        PACK2(q2[d / 2 + 1], t4.z * 0.125f, t4.w * 0.125f);
    }
    float m = -1e30f, l = 0.f;
    uint64_t acc2[32];
    #pragma unroll
    for (int i = 0; i < 32; i++) acc2[i] = 0ull;   // {0.f, 0.f}

    for (int j = 0; j <= qt; j++) {
        const float* kp = qkv + (size_t)(b * SEQ + j * 64) * 1536 + 1024 + g * HDIM;
        const float* vp = kp + 256;
        __syncthreads();
        #pragma unroll
        for (int i = 0; i < 16; i++) {
            int idx = i * 64 + tid;
            int r = idx >> 4, c = (idx & 15) * 4;
            *(float4*)&Ks[r][c] = *(const float4*)(kp + (size_t)r * 1536 + c);
            *(float4*)&Vs[r][c] = *(const float4*)(vp + (size_t)r * 1536 + c);
        }
        __syncthreads();

        // ---- scores: 2 independent packed chains per key ----
        #pragma unroll
        for (int kk = 0; kk < 64; kk++) {
            uint64_t s01 = 0ull, s23 = 0ull;
            uint32_t ka = ksb + kk * 256;
            #pragma unroll
            for (int d = 0; d < 64; d += 4) {
                uint64_t k01, k23;
                LDS_V2U64(k01, k23, ka + d * 4);
                F32X2_FMA(s01, q2[d / 2], k01);
                F32X2_FMA(s23, q2[d / 2 + 1], k23);
            }
            uint64_t st;
            F32X2_ADD(st, s01, s23);
            float f0, f1;
            UNPACK2(f0, f1, st);
            Ss[kk][tid] = f0 + f1;
        }
        if (j == qt) {
            for (int kk = tid + 1; kk < 64; kk++) Ss[kk][tid] = -1e30f;
        }
        float tmax = -1e30f;
        #pragma unroll
        for (int kk = 0; kk < 64; kk++) tmax = fmaxf(tmax, Ss[kk][tid]);
        float nm = fmaxf(m, tmax);
        float corr = __expf(m - nm);
        l *= corr;
        uint64_t cc;
        PACK2(cc, corr, corr);
        #pragma unroll
        for (int i = 0; i < 32; i++) F32X2_MUL(acc2[i], acc2[i], cc);

        // ---- P·V: packed accumulate ----
        #pragma unroll
        for (int kk = 0; kk < 64; kk++) {
            float p = __expf(Ss[kk][tid] - nm);
            l += p;
            uint64_t pp;
            PACK2(pp, p, p);
            uint32_t va = vsb + kk * 256;
            #pragma unroll
            for (int d = 0; d < 64; d += 4) {
                uint64_t v01, v23;
                LDS_V2U64(v01, v23, va + d * 4);
                F32X2_FMA(acc2[d / 2], pp, v01);
                F32X2_FMA(acc2[d / 2 + 1], pp, v23);
            }
        }
        m = nm;
    }
    float inv = 1.f / l;
    bf16* op = oe + (size_t)(b * SEQ + qi) * 3072 + h * HDIM;
    #pragma unroll
    for (int d = 0; d < 64; d += 2) {
        float a0, a1;
        UNPACK2(a0, a1, acc2[d / 2]);
        float y0 = a0 * inv, y1 = a1 * inv;
        bf16 h0, l0, h1, l1;
        split2(y0, h0, l0); split2(y1, h1, l1);
        *(__nv_bfloat162*)(op + d)        = __nv_bfloat162(h0, h1);
        *(__nv_bfloat162*)(op + 1024 + d) = __nv_bfloat162(h0, h1);
        *(__nv_bfloat162*)(op + 2048 + d) = __nv_bfloat162(l0, l1);
    }
}

// ---------------- SwiGLU -> fp16 2K [hi|lo], 4 elems/thread ----------------
__global__ void swiglu_expand_f16_kernel() {
    int i4 = (blockIdx.x * 256 + threadIdx.x) * 4;   // over TOK*FF
    int t = i4 >> 12, c = i4 & 4095;
    float4 a4 = *(const float4*)(g_f13 + (size_t)t * 8192 + c);
    float4 b4 = *(const float4*)(g_f13 + (size_t)t * 8192 + 4096 + c);
    float as[4] = {a4.x, a4.y, a4.z, a4.w};
    float bs[4] = {b4.x, b4.y, b4.z, b4.w};
    __half hi[4], lo[4];
    #pragma unroll
    for (int i = 0; i < 4; i++) {
        float u = (as[i] / (1.f + __expf(-as[i]))) * bs[i];
        split2h(u, hi[i], lo[i]);
    }
    __half* o = g_f1h + (size_t)t * 8192;
    *(uint2*)(o + c)        = *(uint2*)hi;
    *(uint2*)(o + 4096 + c) = *(uint2*)lo;
}

// ---------------- host orchestration ----------------
extern "C" void kernel_launch(void* const* d_in, const int* in_sizes, int n_in,
                              void* d_out, int out_size) {
    const int*   ids = (const int*)d_in[0];
    const float* emb = (const float*)d_in[1];
    const float* wq  = (const float*)d_in[2];
    const float* wk  = (const float*)d_in[3];
    const float* wv  = (const float*)d_in[4];
    const float* wo  = (const float*)d_in[5];
    const float* n1  = (const float*)d_in[6];
    const float* n2  = (const float*)d_in[7];
    const float* w1  = (const float*)d_in[8];
    const float* w2  = (const float*)d_in[9];
    const float* w3  = (const float*)d_in[10];
    const float* fnw = (const float*)d_in[11];
    float* out = (float*)d_out;

    static int smem_set = 0;
    if (!smem_set) {
        cudaFuncSetAttribute(gemm_b16<0,0>, cudaFuncAttributeMaxDynamicSharedMemorySize, SMEM_DYN);
        cudaFuncSetAttribute(gemm_b16<1,0>, cudaFuncAttributeMaxDynamicSharedMemorySize, SMEM_DYN);
        cudaFuncSetAttribute(gemm_b16<0,1>, cudaFuncAttributeMaxDynamicSharedMemorySize, SMEM_DYN);
        cudaFuncSetAttribute(gemm_b16<1,1>, cudaFuncAttributeMaxDynamicSharedMemorySize, SMEM_DYN);
        smem_set = 1;
    }

    float *h, *qkv, *f13;
    bf16 *xne, *atte, *ewqkv, *ewo;
    __half *xnh, *f1h, *ew13h, *ew2h, *eembh;
    cudaGetSymbolAddress((void**)&h,     g_h);
    cudaGetSymbolAddress((void**)&qkv,   g_qkv);
    cudaGetSymbolAddress((void**)&f13,   g_f13);
    cudaGetSymbolAddress((void**)&xne,   g_xne);
    cudaGetSymbolAddress((void**)&atte,  g_atte);
    cudaGetSymbolAddress((void**)&xnh,   g_xnh);
    cudaGetSymbolAddress((void**)&f1h,   g_f1h);
    cudaGetSymbolAddress((void**)&ewqkv, e_wqkv);
    cudaGetSymbolAddress((void**)&ewo,   e_wo);
    cudaGetSymbolAddress((void**)&ew13h, e_w13h);
    cudaGetSymbolAddress((void**)&ew2h,  e_w2h);
    cudaGetSymbolAddress((void**)&eembh, e_embh);

    // ---- expand weights: bf16 3K for qkv/wo, fp16 2K for w13/w2/emb ----
    expand_w_kernel<<<(NLAYER * 1024 * 1024) / 2048, 256>>>(wq, ewqkv, 1024, 1024, (size_t)1536 * 3072, 0);
    expand_w_kernel<<<(NLAYER * 256  * 1024) / 2048, 256>>>(wk, ewqkv, 1024, 256,  (size_t)1536 * 3072, 1024);
    expand_w_kernel<<<(NLAYER * 256  * 1024) / 2048, 256>>>(wv, ewqkv, 1024, 256,  (size_t)1536 * 3072, 1280);
    expand_w_kernel<<<(NLAYER * 1024 * 1024) / 2048, 256>>>(wo, ewo,   1024, 1024, (size_t)1024 * 3072, 0);
    expand_w_f16_kernel<<<(NLAYER * 4096 * 1024) / 2048, 256>>>(w1, ew13h, 1024, 4096, (size_t)8192 * 2048, 0);
    expand_w_f16_kernel<<<(NLAYER * 4096 * 1024) / 2048, 256>>>(w3, ew13h, 1024, 4096, (size_t)8192 * 2048, 4096);
    expand_w_f16_kernel<<<(NLAYER * 1024 * 4096) / 2048, 256>>>(w2, ew2h,  4096, 1024, (size_t)1024 * 8192, 0);
    expand_w_f16_kernel<<<(VOCAB * 1024) / 2048, 256>>>(emb, eembh, 1024, VOCAB, 0, 0);

    rope_init_kernel<<<SEQ, 32>>>();
    embed_kernel<<<TOK, 256>>>(ids, emb);

    for (int l = 0; l < NLAYER; l++) {
        // --- attention block: bf16 3K (proven path) ---
        rmsnorm_expand_kernel<<<TOK, 256>>>(h, n1 + (size_t)l * DIM, xne);
        gemm_b16<0,0><<<dim3(1536 / BN, TOK / BM), 256, SMEM_DYN>>>(
            (const uint16_t*)xne, (const uint16_t*)(ewqkv + (size_t)l * 1536 * 3072),
            nullptr, qkv, 1536, 3072);
        rope_kernel<<<(TOK * NHEAD * 32) / 256, 256>>>(qkv, NHEAD, 0);
        rope_kernel<<<(TOK * KVHEAD * 32) / 256, 256>>>(qkv, KVHEAD, 1024);
        attn_kernel<<<dim3(SEQ / 64, NHEAD, BATCH), 64>>>(qkv, atte);
        gemm_b16<1,0><<<dim3(1024 / BN, TOK / BM), 256, SMEM_DYN>>>(
            (const uint16_t*)atte, (const uint16_t*)(ewo + (size_t)l * 1024 * 3072),
            h, h, 1024, 3072);
        // --- FFN block: fp16 2K ---
        rmsnorm_expand_f16_kernel<<<TOK, 256>>>(h, n2 + (size_t)l * DIM, xnh);
        gemm_b16<0,1><<<dim3(8192 / BN, TOK / BM), 256, SMEM_DYN>>>(
            (const uint16_t*)xnh, (const uint16_t*)(ew13h + (size_t)l * 8192 * 2048),
            nullptr, f13, 8192, 2048);
        swiglu_expand_f16_kernel<<<(TOK * FF) / 1024, 256>>>();
        gemm_b16<1,1><<<dim3(1024 / BN, TOK / BM), 256, SMEM_DYN>>>(
            (const uint16_t*)f1h, (const uint16_t*)(ew2h + (size_t)l * 1024 * 8192),
            h, h, 1024, 8192);
    }
    // --- logits: fp16 2K ---
    rmsnorm_expand_f16_kernel<<<TOK, 256>>>(h, fnw, xnh);
    gemm_b16<0,1><<<dim3(VOCAB / BN, TOK / BM), 256, SMEM_DYN>>>(
        (const uint16_t*)xnh, (const uint16_t*)eembh, nullptr, out, VOCAB, 2048);
}